// round 1
// baseline (speedup 1.0000x reference)
#include <cuda_runtime.h>
#include <math.h>

#define D_MODEL 1024
#define NHEAD 16
#define HEAD_DIM 64
#define BATCH 2
#define SEQ 2048
#define M_TOTAL (BATCH * SEQ)      /* 4096 */
#define N_QKV (3 * D_MODEL)        /* 3072 */

/* -------- scratch (static device arrays: allocation-free) -------- */
__device__ float g_xn[M_TOTAL * D_MODEL];                       /* 16 MB */
__device__ float g_q[BATCH * NHEAD * SEQ * HEAD_DIM];           /* 16 MB */
__device__ float g_k[BATCH * NHEAD * SEQ * HEAD_DIM];
__device__ float g_v[BATCH * NHEAD * SEQ * HEAD_DIM];

/* ================= LayerNorm: one block per row ================= */
__global__ __launch_bounds__(256) void ln_kernel(const float* __restrict__ x,
                                                 const float* __restrict__ gamma,
                                                 const float* __restrict__ beta) {
    int row = blockIdx.x;
    const float* xr = x + (size_t)row * D_MODEL;
    float* outr = g_xn + (size_t)row * D_MODEL;

    float v[4];
    float s = 0.f, ss = 0.f;
#pragma unroll
    for (int i = 0; i < 4; i++) {
        float t = xr[threadIdx.x + i * 256];
        v[i] = t; s += t; ss += t * t;
    }
    __shared__ float rs[8], rss[8];
#pragma unroll
    for (int o = 16; o > 0; o >>= 1) {
        s  += __shfl_xor_sync(0xffffffffu, s, o);
        ss += __shfl_xor_sync(0xffffffffu, ss, o);
    }
    if ((threadIdx.x & 31) == 0) { rs[threadIdx.x >> 5] = s; rss[threadIdx.x >> 5] = ss; }
    __syncthreads();
    if (threadIdx.x < 32) {
        s  = (threadIdx.x < 8) ? rs[threadIdx.x]  : 0.f;
        ss = (threadIdx.x < 8) ? rss[threadIdx.x] : 0.f;
#pragma unroll
        for (int o = 4; o > 0; o >>= 1) {
            s  += __shfl_xor_sync(0xffffffffu, s, o);
            ss += __shfl_xor_sync(0xffffffffu, ss, o);
        }
        if (threadIdx.x == 0) { rs[0] = s; rss[0] = ss; }
    }
    __syncthreads();
    float mean = rs[0] * (1.f / D_MODEL);
    float var  = rss[0] * (1.f / D_MODEL) - mean * mean;
    float rstd = rsqrtf(var + 1e-5f);
#pragma unroll
    for (int i = 0; i < 4; i++) {
        int c = threadIdx.x + i * 256;
        outr[c] = (v[i] - mean) * rstd * gamma[c] + beta[c];
    }
}

/* ========== QKV GEMM: C[m,n] = xn[m,:]·W[n,:] + b[n] ==========
   64x64 tile, BK=16, 256 threads, 4x4 microtile.
   Epilogue scatters into Q/K/V with [B,H,L,Dh] layout. */
#define BM 64
#define BN 64
#define BK 16
__global__ __launch_bounds__(256) void qkv_gemm(const float* __restrict__ w,
                                                const float* __restrict__ bias) {
    __shared__ float As[BK][BM + 1];
    __shared__ float Bs[BK][BN + 1];
    int m0 = blockIdx.y * BM;
    int n0 = blockIdx.x * BN;
    int tid = threadIdx.x;
    int tx = tid & 15, ty = tid >> 4;
    int lr = tid >> 2, lsg = tid & 3;     /* loader: row 0..63, float4 segment 0..3 */

    float acc[4][4] = {};
    for (int k0 = 0; k0 < D_MODEL; k0 += BK) {
        float4 a4 = *(const float4*)(g_xn + (size_t)(m0 + lr) * D_MODEL + k0 + lsg * 4);
        float4 b4 = *(const float4*)(w    + (size_t)(n0 + lr) * D_MODEL + k0 + lsg * 4);
        As[lsg * 4 + 0][lr] = a4.x; As[lsg * 4 + 1][lr] = a4.y;
        As[lsg * 4 + 2][lr] = a4.z; As[lsg * 4 + 3][lr] = a4.w;
        Bs[lsg * 4 + 0][lr] = b4.x; Bs[lsg * 4 + 1][lr] = b4.y;
        Bs[lsg * 4 + 2][lr] = b4.z; Bs[lsg * 4 + 3][lr] = b4.w;
        __syncthreads();
#pragma unroll
        for (int k = 0; k < BK; k++) {
            float a[4], b[4];
#pragma unroll
            for (int i = 0; i < 4; i++) a[i] = As[k][ty * 4 + i];
#pragma unroll
            for (int j = 0; j < 4; j++) b[j] = Bs[k][tx * 4 + j];
#pragma unroll
            for (int i = 0; i < 4; i++)
#pragma unroll
                for (int j = 0; j < 4; j++) acc[i][j] += a[i] * b[j];
        }
        __syncthreads();
    }
#pragma unroll
    for (int i = 0; i < 4; i++) {
        int m = m0 + ty * 4 + i;
        int bb = m / SEQ, l = m % SEQ;
#pragma unroll
        for (int j = 0; j < 4; j++) {
            int n = n0 + tx * 4 + j;
            float c = acc[i][j] + bias[n];
            int t = n / D_MODEL;
            int hd = n % D_MODEL;
            int h = hd >> 6, d = hd & 63;
            float* dst = (t == 0) ? g_q : (t == 1) ? g_k : g_v;
            dst[((((size_t)bb * NHEAD + h) * SEQ) + l) * HEAD_DIM + d] = c;
        }
    }
}

/* ========== Flash attention, fp32, online softmax ==========
   Block: (q-tile of 64 rows) x (one b,h). 256 threads = 16x16, 4x4 microtile.
   Per K-tile of 64: S = Qs·Ksᵀ, softmax update, P staged to smem, O += P·Vs. */
#define PITCH 65
#define ATTN_SMEM (4 * 64 * PITCH * (int)sizeof(float))   /* 66560 B */

__global__ __launch_bounds__(256) void attn_kernel(float* __restrict__ out) {
    extern __shared__ float sm[];
    float* Qs = sm;
    float* Ks = Qs + 64 * PITCH;
    float* Vs = Ks + 64 * PITCH;
    float* Ps = Vs + 64 * PITCH;

    int bh = blockIdx.y;                 /* 0..31 */
    int b = bh / NHEAD, h = bh % NHEAD;
    int q0 = blockIdx.x * 64;
    const float* Q = g_q + (size_t)bh * SEQ * HEAD_DIM;
    const float* K = g_k + (size_t)bh * SEQ * HEAD_DIM;
    const float* V = g_v + (size_t)bh * SEQ * HEAD_DIM;

    int tid = threadIdx.x;
    int tx = tid & 15, ty = tid >> 4;

    /* load Q tile, fold in softmax scale 1/sqrt(64) = 0.125 */
    for (int i = tid; i < 64 * 64; i += 256) {
        int r = i >> 6, c = i & 63;
        Qs[r * PITCH + c] = Q[(size_t)(q0 + r) * 64 + c] * 0.125f;
    }

    float m_i[4], l_i[4], o[4][4] = {};
#pragma unroll
    for (int i = 0; i < 4; i++) { m_i[i] = -1e30f; l_i[i] = 0.f; }

    for (int k0 = 0; k0 < SEQ; k0 += 64) {
        __syncthreads();   /* prev iteration done with Ks/Vs/Ps (and Qs load done) */
        for (int i = tid; i < 64 * 64; i += 256) {
            int r = i >> 6, c = i & 63;
            Ks[r * PITCH + c] = K[(size_t)(k0 + r) * 64 + c];
            Vs[r * PITCH + c] = V[(size_t)(k0 + r) * 64 + c];
        }
        __syncthreads();

        /* S = Qs · Ksᵀ  (4x4 per thread) */
        float s[4][4] = {};
#pragma unroll 8
        for (int d = 0; d < 64; d++) {
            float a[4], bb[4];
#pragma unroll
            for (int i = 0; i < 4; i++) a[i] = Qs[(ty * 4 + i) * PITCH + d];
#pragma unroll
            for (int j = 0; j < 4; j++) bb[j] = Ks[(tx * 4 + j) * PITCH + d];
#pragma unroll
            for (int i = 0; i < 4; i++)
#pragma unroll
                for (int j = 0; j < 4; j++) s[i][j] += a[i] * bb[j];
        }

        /* online softmax per q row; rows span 16 contiguous lanes (width-16 xor ok) */
#pragma unroll
        for (int i = 0; i < 4; i++) {
            float mx = s[i][0];
#pragma unroll
            for (int j = 1; j < 4; j++) mx = fmaxf(mx, s[i][j]);
#pragma unroll
            for (int off = 8; off > 0; off >>= 1)
                mx = fmaxf(mx, __shfl_xor_sync(0xffffffffu, mx, off));
            float m_new = fmaxf(m_i[i], mx);
            float alpha = __expf(m_i[i] - m_new);
            float rsum = 0.f;
#pragma unroll
            for (int j = 0; j < 4; j++) {
                float p = __expf(s[i][j] - m_new);
                s[i][j] = p; rsum += p;
            }
#pragma unroll
            for (int off = 8; off > 0; off >>= 1)
                rsum += __shfl_xor_sync(0xffffffffu, rsum, off);
            l_i[i] = l_i[i] * alpha + rsum;
            m_i[i] = m_new;
#pragma unroll
            for (int j = 0; j < 4; j++) {
                o[i][j] *= alpha;
                Ps[(ty * 4 + i) * PITCH + tx * 4 + j] = s[i][j];
            }
        }
        __syncthreads();

        /* O += Ps · Vs */
#pragma unroll 8
        for (int k = 0; k < 64; k++) {
            float a[4], bb[4];
#pragma unroll
            for (int i = 0; i < 4; i++) a[i] = Ps[(ty * 4 + i) * PITCH + k];
#pragma unroll
            for (int j = 0; j < 4; j++) bb[j] = Vs[k * PITCH + tx * 4 + j];
#pragma unroll
            for (int i = 0; i < 4; i++)
#pragma unroll
                for (int j = 0; j < 4; j++) o[i][j] += a[i] * bb[j];
        }
    }

    /* out[b][l][h*64 + d] */
#pragma unroll
    for (int i = 0; i < 4; i++) {
        float inv = 1.f / l_i[i];
        int l = q0 + ty * 4 + i;
#pragma unroll
        for (int j = 0; j < 4; j++) {
            out[((size_t)b * SEQ + l) * D_MODEL + h * 64 + tx * 4 + j] = o[i][j] * inv;
        }
    }
}

/* ======================= launch ======================= */
extern "C" void kernel_launch(void* const* d_in, const int* in_sizes, int n_in,
                              void* d_out, int out_size) {
    const float* x     = (const float*)d_in[0];
    const float* w_qkv = (const float*)d_in[1];
    const float* b_qkv = (const float*)d_in[2];
    const float* gamma = (const float*)d_in[3];
    const float* beta  = (const float*)d_in[4];
    float* out = (float*)d_out;

    (void)in_sizes; (void)n_in; (void)out_size;

    /* opt-in >48KB dynamic smem for attention (idempotent; cheap) */
    cudaFuncSetAttribute(attn_kernel, cudaFuncAttributeMaxDynamicSharedMemorySize,
                         ATTN_SMEM);

    ln_kernel<<<M_TOTAL, 256>>>(x, gamma, beta);

    dim3 ggrid(N_QKV / BN, M_TOTAL / BM);
    qkv_gemm<<<ggrid, 256>>>(w_qkv, b_qkv);

    dim3 agrid(SEQ / 64, BATCH * NHEAD);
    attn_kernel<<<agrid, 256, ATTN_SMEM>>>(out);
}

// round 2
// speedup vs baseline: 3.1935x; 3.1935x over previous
#include <cuda_runtime.h>
#include <cuda_bf16.h>
#include <math.h>
#include <stdint.h>

#define D_MODEL 1024
#define NHEAD 16
#define HEAD_DIM 64
#define BATCH 2
#define SEQ 2048
#define M_TOTAL (BATCH * SEQ)      /* 4096 */
#define N_QKV (3 * D_MODEL)        /* 3072 */

/* -------- scratch (static device arrays: allocation-free) -------- */
__device__ float g_xn[M_TOTAL * D_MODEL];
__device__ float g_q[BATCH * NHEAD * SEQ * HEAD_DIM];
__device__ float g_k[BATCH * NHEAD * SEQ * HEAD_DIM];
__device__ float g_v[BATCH * NHEAD * SEQ * HEAD_DIM];

/* ================= helpers ================= */
__device__ __forceinline__ uint32_t smem_u32(const void* p) {
    return (uint32_t)__cvta_generic_to_shared(p);
}

__device__ __forceinline__ void ldsm_x4(uint32_t& r0, uint32_t& r1, uint32_t& r2,
                                        uint32_t& r3, uint32_t addr) {
    asm volatile("ldmatrix.sync.aligned.m8n8.x4.shared.b16 {%0,%1,%2,%3}, [%4];"
                 : "=r"(r0), "=r"(r1), "=r"(r2), "=r"(r3) : "r"(addr));
}
__device__ __forceinline__ void ldsm_x2(uint32_t& r0, uint32_t& r1, uint32_t addr) {
    asm volatile("ldmatrix.sync.aligned.m8n8.x2.shared.b16 {%0,%1}, [%2];"
                 : "=r"(r0), "=r"(r1) : "r"(addr));
}
__device__ __forceinline__ void ldsm_x2t(uint32_t& r0, uint32_t& r1, uint32_t addr) {
    asm volatile("ldmatrix.sync.aligned.m8n8.x2.trans.shared.b16 {%0,%1}, [%2];"
                 : "=r"(r0), "=r"(r1) : "r"(addr));
}

__device__ __forceinline__ void mma_bf16(float* c, uint32_t a0, uint32_t a1,
                                         uint32_t a2, uint32_t a3,
                                         uint32_t b0, uint32_t b1) {
    asm volatile(
        "mma.sync.aligned.m16n8k16.row.col.f32.bf16.bf16.f32 "
        "{%0,%1,%2,%3}, {%4,%5,%6,%7}, {%8,%9}, {%0,%1,%2,%3};"
        : "+f"(c[0]), "+f"(c[1]), "+f"(c[2]), "+f"(c[3])
        : "r"(a0), "r"(a1), "r"(a2), "r"(a3), "r"(b0), "r"(b1));
}

/* pack two floats' bf16-truncated HI halves into one .b32 (low = first) */
__device__ __forceinline__ uint32_t pack_hi(float x, float y) {
    return (__float_as_uint(x) >> 16) | (__float_as_uint(y) & 0xFFFF0000u);
}
/* residual LO halves, rounded to bf16 */
__device__ __forceinline__ uint32_t pack_lo(float x, float y) {
    float xh = __uint_as_float(__float_as_uint(x) & 0xFFFF0000u);
    float yh = __uint_as_float(__float_as_uint(y) & 0xFFFF0000u);
    __nv_bfloat162 t = __floats2bfloat162_rn(x - xh, y - yh);
    return *reinterpret_cast<uint32_t*>(&t);
}

/* ================= LayerNorm: one block per row ================= */
__global__ __launch_bounds__(256) void ln_kernel(const float* __restrict__ x,
                                                 const float* __restrict__ gamma,
                                                 const float* __restrict__ beta) {
    int row = blockIdx.x;
    const float* xr = x + (size_t)row * D_MODEL;
    float* outr = g_xn + (size_t)row * D_MODEL;

    float v[4];
    float s = 0.f, ss = 0.f;
#pragma unroll
    for (int i = 0; i < 4; i++) {
        float t = xr[threadIdx.x + i * 256];
        v[i] = t; s += t; ss += t * t;
    }
    __shared__ float rs[8], rss[8];
#pragma unroll
    for (int o = 16; o > 0; o >>= 1) {
        s  += __shfl_xor_sync(0xffffffffu, s, o);
        ss += __shfl_xor_sync(0xffffffffu, ss, o);
    }
    if ((threadIdx.x & 31) == 0) { rs[threadIdx.x >> 5] = s; rss[threadIdx.x >> 5] = ss; }
    __syncthreads();
    if (threadIdx.x < 32) {
        s  = (threadIdx.x < 8) ? rs[threadIdx.x]  : 0.f;
        ss = (threadIdx.x < 8) ? rss[threadIdx.x] : 0.f;
#pragma unroll
        for (int o = 4; o > 0; o >>= 1) {
            s  += __shfl_xor_sync(0xffffffffu, s, o);
            ss += __shfl_xor_sync(0xffffffffu, ss, o);
        }
        if (threadIdx.x == 0) { rs[0] = s; rss[0] = ss; }
    }
    __syncthreads();
    float mean = rs[0] * (1.f / D_MODEL);
    float var  = rss[0] * (1.f / D_MODEL) - mean * mean;
    float rstd = rsqrtf(var + 1e-5f);
#pragma unroll
    for (int i = 0; i < 4; i++) {
        int c = threadIdx.x + i * 256;
        outr[c] = (v[i] - mean) * rstd * gamma[c] + beta[c];
    }
}

/* ========== QKV GEMM via bf16 MMA, 3-term split ==========
   C[m,n] = xn[m,:]·W[n,:] + b[n]; 128x128x32 block tile, 8 warps (2x4),
   warp tile 64x32 (4 m-tiles x 4 n-tiles of m16n8k16). */
#define GBM 128
#define GBN 128
#define GBK 32
#define GP  40   /* smem pitch (bf16 elems) -> 80B row stride, ldmatrix conflict-free */

__global__ __launch_bounds__(256) void qkv_gemm(const float* __restrict__ w,
                                                const float* __restrict__ bias) {
    __shared__ unsigned short Ah[GBM * GP], Al[GBM * GP];
    __shared__ unsigned short Bh[GBN * GP], Bl[GBN * GP];

    int m0 = blockIdx.y * GBM;
    int n0 = blockIdx.x * GBN;
    int tid = threadIdx.x;
    int lane = tid & 31, wrp = tid >> 5;
    int wm = (wrp >> 2) * 64, wn = (wrp & 3) * 32;
    int t4 = lane >> 2, qp = lane & 3;
    int l16 = lane & 15;

    int lr = tid >> 3, lseg = tid & 7;  /* loader: 32 rows/pass, 8 float4 segs */

    float acc[4][4][4];
#pragma unroll
    for (int i = 0; i < 4; i++)
#pragma unroll
        for (int j = 0; j < 4; j++)
#pragma unroll
            for (int c = 0; c < 4; c++) acc[i][j][c] = 0.f;

    for (int k0 = 0; k0 < D_MODEL; k0 += GBK) {
#pragma unroll
        for (int p = 0; p < 4; p++) {
            int row = lr + p * 32;
            float4 a4 = *(const float4*)(g_xn + (size_t)(m0 + row) * D_MODEL + k0 + lseg * 4);
            float4 b4 = *(const float4*)(w    + (size_t)(n0 + row) * D_MODEL + k0 + lseg * 4);
            int off = row * GP + lseg * 4;
            *(uint32_t*)&Ah[off]     = pack_hi(a4.x, a4.y);
            *(uint32_t*)&Ah[off + 2] = pack_hi(a4.z, a4.w);
            *(uint32_t*)&Al[off]     = pack_lo(a4.x, a4.y);
            *(uint32_t*)&Al[off + 2] = pack_lo(a4.z, a4.w);
            *(uint32_t*)&Bh[off]     = pack_hi(b4.x, b4.y);
            *(uint32_t*)&Bh[off + 2] = pack_hi(b4.z, b4.w);
            *(uint32_t*)&Bl[off]     = pack_lo(b4.x, b4.y);
            *(uint32_t*)&Bl[off + 2] = pack_lo(b4.z, b4.w);
        }
        __syncthreads();

#pragma unroll
        for (int ks = 0; ks < 2; ks++) {
            uint32_t ah[4][4], al[4][4];
#pragma unroll
            for (int mt = 0; mt < 4; mt++) {
                int arow = wm + mt * 16 + l16;
                int acol = ks * 16 + (lane >> 4) * 8;
                ldsm_x4(ah[mt][0], ah[mt][1], ah[mt][2], ah[mt][3],
                        smem_u32(&Ah[arow * GP + acol]));
                ldsm_x4(al[mt][0], al[mt][1], al[mt][2], al[mt][3],
                        smem_u32(&Al[arow * GP + acol]));
            }
#pragma unroll
            for (int nt = 0; nt < 4; nt++) {
                int brow = wn + nt * 8 + (l16 & 7);
                int bcol = ks * 16 + (l16 >> 3) * 8;
                uint32_t bh0, bh1, bl0, bl1;
                ldsm_x2(bh0, bh1, smem_u32(&Bh[brow * GP + bcol]));
                ldsm_x2(bl0, bl1, smem_u32(&Bl[brow * GP + bcol]));
#pragma unroll
                for (int mt = 0; mt < 4; mt++) {
                    mma_bf16(acc[mt][nt], ah[mt][0], ah[mt][1], ah[mt][2], ah[mt][3], bh0, bh1);
                    mma_bf16(acc[mt][nt], ah[mt][0], ah[mt][1], ah[mt][2], ah[mt][3], bl0, bl1);
                    mma_bf16(acc[mt][nt], al[mt][0], al[mt][1], al[mt][2], al[mt][3], bh0, bh1);
                }
            }
        }
        __syncthreads();
    }

    /* epilogue: bias + scatter into Q/K/V [B,H,L,Dh] */
#pragma unroll
    for (int mt = 0; mt < 4; mt++) {
        int mbase = m0 + wm + mt * 16 + t4;
#pragma unroll
        for (int nt = 0; nt < 4; nt++) {
            int n = n0 + wn + nt * 8 + qp * 2;
            int t = n >> 10;
            int hd = n & 1023;
            int h = hd >> 6, d = hd & 63;
            float* dst = (t == 0) ? g_q : (t == 1) ? g_k : g_v;
            float bv0 = bias[n], bv1 = bias[n + 1];
            int r0 = mbase, r1 = mbase + 8;
            int bb0 = r0 >> 11, l0 = r0 & 2047;
            int bb1 = r1 >> 11, l1 = r1 & 2047;
            float2 v0 = make_float2(acc[mt][nt][0] + bv0, acc[mt][nt][1] + bv1);
            float2 v1 = make_float2(acc[mt][nt][2] + bv0, acc[mt][nt][3] + bv1);
            *(float2*)&dst[((((size_t)bb0 * NHEAD + h) * SEQ) + l0) * HEAD_DIM + d] = v0;
            *(float2*)&dst[((((size_t)bb1 * NHEAD + h) * SEQ) + l1) * HEAD_DIM + d] = v1;
        }
    }
}

/* ========== Flash attention, bf16 MMA 3-term split ==========
   Block: 128 q-rows x (b,h). 8 warps, each warp 16 q-rows.
   K-tile = 64 keys. S = Q·K^T (mma), online softmax in fp32 on fragments,
   P repacked from S regs -> A frags, O += P·V (V via ldmatrix.trans). */
#define AQ 128
#define AP 72    /* smem pitch (bf16 elems) -> 144B, conflict-free for ldmatrix */
#define ATTN_SMEM ((AQ * AP * 2 + 64 * AP * 4) * (int)sizeof(unsigned short)) /* 73728 */

__global__ __launch_bounds__(256) void attn_kernel(float* __restrict__ out) {
    extern __shared__ unsigned short sm[];
    unsigned short* Qh = sm;
    unsigned short* Ql = Qh + AQ * AP;
    unsigned short* Kh = Ql + AQ * AP;
    unsigned short* Kl = Kh + 64 * AP;
    unsigned short* Vh = Kl + 64 * AP;
    unsigned short* Vl = Vh + 64 * AP;

    int bh = blockIdx.y;
    int b = bh / NHEAD, h = bh % NHEAD;
    int q0 = blockIdx.x * AQ;
    const float* Q = g_q + (size_t)bh * SEQ * HEAD_DIM;
    const float* K = g_k + (size_t)bh * SEQ * HEAD_DIM;
    const float* V = g_v + (size_t)bh * SEQ * HEAD_DIM;

    int tid = threadIdx.x;
    int lane = tid & 31, wrp = tid >> 5;
    int t4 = lane >> 2, qp = lane & 3;
    int l16 = lane & 15;

    /* load Q tile (scaled by 1/8) into hi/lo planes */
    {
        int seg = tid & 15;
#pragma unroll
        for (int p = 0; p < 8; p++) {
            int row = (tid >> 4) + p * 16;
            float4 q4 = *(const float4*)(Q + (size_t)(q0 + row) * HEAD_DIM + seg * 4);
            q4.x *= 0.125f; q4.y *= 0.125f; q4.z *= 0.125f; q4.w *= 0.125f;
            int off = row * AP + seg * 4;
            *(uint32_t*)&Qh[off]     = pack_hi(q4.x, q4.y);
            *(uint32_t*)&Qh[off + 2] = pack_hi(q4.z, q4.w);
            *(uint32_t*)&Ql[off]     = pack_lo(q4.x, q4.y);
            *(uint32_t*)&Ql[off + 2] = pack_lo(q4.z, q4.w);
        }
    }

    float m_i[2] = {-1e30f, -1e30f};
    float l_i[2] = {0.f, 0.f};
    float O[8][4];
#pragma unroll
    for (int i = 0; i < 8; i++)
#pragma unroll
        for (int c = 0; c < 4; c++) O[i][c] = 0.f;

    for (int kt = 0; kt < SEQ / 64; kt++) {
        int k0 = kt * 64;
        __syncthreads();
        {
            int seg = tid & 15;
#pragma unroll
            for (int p = 0; p < 4; p++) {
                int row = (tid >> 4) + p * 16;
                float4 k4 = *(const float4*)(K + (size_t)(k0 + row) * HEAD_DIM + seg * 4);
                float4 v4 = *(const float4*)(V + (size_t)(k0 + row) * HEAD_DIM + seg * 4);
                int off = row * AP + seg * 4;
                *(uint32_t*)&Kh[off]     = pack_hi(k4.x, k4.y);
                *(uint32_t*)&Kh[off + 2] = pack_hi(k4.z, k4.w);
                *(uint32_t*)&Kl[off]     = pack_lo(k4.x, k4.y);
                *(uint32_t*)&Kl[off + 2] = pack_lo(k4.z, k4.w);
                *(uint32_t*)&Vh[off]     = pack_hi(v4.x, v4.y);
                *(uint32_t*)&Vh[off + 2] = pack_hi(v4.z, v4.w);
                *(uint32_t*)&Vl[off]     = pack_lo(v4.x, v4.y);
                *(uint32_t*)&Vl[off + 2] = pack_lo(v4.z, v4.w);
            }
        }
        __syncthreads();

        /* S = Q·K^T  (8 n-tiles of keys, 4 k16 steps over Dh=64) */
        float S[8][4];
#pragma unroll
        for (int i = 0; i < 8; i++)
#pragma unroll
            for (int c = 0; c < 4; c++) S[i][c] = 0.f;

#pragma unroll
        for (int ks = 0; ks < 4; ks++) {
            int arow = wrp * 16 + l16;
            int acol = ks * 16 + (lane >> 4) * 8;
            uint32_t qh0, qh1, qh2, qh3, ql0, ql1, ql2, ql3;
            ldsm_x4(qh0, qh1, qh2, qh3, smem_u32(&Qh[arow * AP + acol]));
            ldsm_x4(ql0, ql1, ql2, ql3, smem_u32(&Ql[arow * AP + acol]));
#pragma unroll
            for (int nt = 0; nt < 8; nt++) {
                int brow = nt * 8 + (l16 & 7);
                int bcol = ks * 16 + (l16 >> 3) * 8;
                uint32_t kh0, kh1, kl0, kl1;
                ldsm_x2(kh0, kh1, smem_u32(&Kh[brow * AP + bcol]));
                ldsm_x2(kl0, kl1, smem_u32(&Kl[brow * AP + bcol]));
                mma_bf16(S[nt], qh0, qh1, qh2, qh3, kh0, kh1);
                mma_bf16(S[nt], qh0, qh1, qh2, qh3, kl0, kl1);
                mma_bf16(S[nt], ql0, ql1, ql2, ql3, kh0, kh1);
            }
        }

        /* online softmax (rows r=t4 and r+8 live in c0/c1 and c2/c3) */
        float mx0 = S[0][0], mx1 = S[0][2];
#pragma unroll
        for (int nt = 0; nt < 8; nt++) {
            mx0 = fmaxf(mx0, fmaxf(S[nt][0], S[nt][1]));
            mx1 = fmaxf(mx1, fmaxf(S[nt][2], S[nt][3]));
        }
#pragma unroll
        for (int o = 1; o <= 2; o <<= 1) {
            mx0 = fmaxf(mx0, __shfl_xor_sync(0xffffffffu, mx0, o));
            mx1 = fmaxf(mx1, __shfl_xor_sync(0xffffffffu, mx1, o));
        }
        float mn0 = fmaxf(m_i[0], mx0), mn1 = fmaxf(m_i[1], mx1);
        float al0 = __expf(m_i[0] - mn0), al1 = __expf(m_i[1] - mn1);
        float sum0 = 0.f, sum1 = 0.f;
#pragma unroll
        for (int nt = 0; nt < 8; nt++) {
            S[nt][0] = __expf(S[nt][0] - mn0);
            S[nt][1] = __expf(S[nt][1] - mn0);
            S[nt][2] = __expf(S[nt][2] - mn1);
            S[nt][3] = __expf(S[nt][3] - mn1);
            sum0 += S[nt][0] + S[nt][1];
            sum1 += S[nt][2] + S[nt][3];
        }
#pragma unroll
        for (int o = 1; o <= 2; o <<= 1) {
            sum0 += __shfl_xor_sync(0xffffffffu, sum0, o);
            sum1 += __shfl_xor_sync(0xffffffffu, sum1, o);
        }
        l_i[0] = l_i[0] * al0 + sum0;
        l_i[1] = l_i[1] * al1 + sum1;
        m_i[0] = mn0; m_i[1] = mn1;
#pragma unroll
        for (int dn = 0; dn < 8; dn++) {
            O[dn][0] *= al0; O[dn][1] *= al0;
            O[dn][2] *= al1; O[dn][3] *= al1;
        }

        /* O += P·V  — P frags straight from S regs (hi + lo split) */
#pragma unroll
        for (int ks2 = 0; ks2 < 4; ks2++) {
            uint32_t ph0 = pack_hi(S[2 * ks2][0],     S[2 * ks2][1]);
            uint32_t ph1 = pack_hi(S[2 * ks2][2],     S[2 * ks2][3]);
            uint32_t ph2 = pack_hi(S[2 * ks2 + 1][0], S[2 * ks2 + 1][1]);
            uint32_t ph3 = pack_hi(S[2 * ks2 + 1][2], S[2 * ks2 + 1][3]);
            uint32_t pl0 = pack_lo(S[2 * ks2][0],     S[2 * ks2][1]);
            uint32_t pl1 = pack_lo(S[2 * ks2][2],     S[2 * ks2][3]);
            uint32_t pl2 = pack_lo(S[2 * ks2 + 1][0], S[2 * ks2 + 1][1]);
            uint32_t pl3 = pack_lo(S[2 * ks2 + 1][2], S[2 * ks2 + 1][3]);
            int vrow = ks2 * 16 + (l16 & 7) + (l16 >> 3) * 8;
#pragma unroll
            for (int dn = 0; dn < 8; dn++) {
                uint32_t vh0, vh1, vl0, vl1;
                ldsm_x2t(vh0, vh1, smem_u32(&Vh[vrow * AP + dn * 8]));
                ldsm_x2t(vl0, vl1, smem_u32(&Vl[vrow * AP + dn * 8]));
                mma_bf16(O[dn], ph0, ph1, ph2, ph3, vh0, vh1);
                mma_bf16(O[dn], ph0, ph1, ph2, ph3, vl0, vl1);
                mma_bf16(O[dn], pl0, pl1, pl2, pl3, vh0, vh1);
            }
        }
    }

    /* out[b][l][h*64 + d] */
    float inv0 = 1.f / l_i[0], inv1 = 1.f / l_i[1];
    int r0 = q0 + wrp * 16 + t4, r1 = r0 + 8;
#pragma unroll
    for (int dn = 0; dn < 8; dn++) {
        int d = h * 64 + dn * 8 + qp * 2;
        float2 v0 = make_float2(O[dn][0] * inv0, O[dn][1] * inv0);
        float2 v1 = make_float2(O[dn][2] * inv1, O[dn][3] * inv1);
        *(float2*)&out[((size_t)b * SEQ + r0) * D_MODEL + d] = v0;
        *(float2*)&out[((size_t)b * SEQ + r1) * D_MODEL + d] = v1;
    }
}

/* ======================= launch ======================= */
extern "C" void kernel_launch(void* const* d_in, const int* in_sizes, int n_in,
                              void* d_out, int out_size) {
    const float* x     = (const float*)d_in[0];
    const float* w_qkv = (const float*)d_in[1];
    const float* b_qkv = (const float*)d_in[2];
    const float* gamma = (const float*)d_in[3];
    const float* beta  = (const float*)d_in[4];
    float* out = (float*)d_out;

    (void)in_sizes; (void)n_in; (void)out_size;

    cudaFuncSetAttribute(attn_kernel, cudaFuncAttributeMaxDynamicSharedMemorySize,
                         ATTN_SMEM);

    ln_kernel<<<M_TOTAL, 256>>>(x, gamma, beta);

    dim3 ggrid(N_QKV / GBN, M_TOTAL / GBM);   /* 24 x 32 */
    qkv_gemm<<<ggrid, 256>>>(w_qkv, b_qkv);

    dim3 agrid(SEQ / AQ, BATCH * NHEAD);      /* 16 x 32 */
    attn_kernel<<<agrid, 256, ATTN_SMEM>>>(out);
}

// round 4
// speedup vs baseline: 3.4167x; 1.0699x over previous
#include <cuda_runtime.h>
#include <cuda_bf16.h>
#include <math.h>
#include <stdint.h>

#define D_MODEL 1024
#define NHEAD 16
#define HEAD_DIM 64
#define BATCH 2
#define SEQ 2048
#define M_TOTAL (BATCH * SEQ)      /* 4096 */
#define N_QKV (3 * D_MODEL)        /* 3072 */
#define QKV_ELEMS (BATCH * NHEAD * SEQ * HEAD_DIM)   /* 4M */

/* -------- bf16 hi/lo planes (static device arrays) -------- */
__device__ unsigned short g_xn_hi[M_TOTAL * D_MODEL];
__device__ unsigned short g_xn_lo[M_TOTAL * D_MODEL];
__device__ unsigned short g_w_hi[N_QKV * D_MODEL];
__device__ unsigned short g_w_lo[N_QKV * D_MODEL];
__device__ unsigned short g_qh[QKV_ELEMS], g_ql[QKV_ELEMS];
__device__ unsigned short g_kh[QKV_ELEMS], g_kl[QKV_ELEMS];
__device__ unsigned short g_vh[QKV_ELEMS], g_vl[QKV_ELEMS];

/* ================= helpers ================= */
__device__ __forceinline__ uint32_t smem_u32(const void* p) {
    return (uint32_t)__cvta_generic_to_shared(p);
}
__device__ __forceinline__ void ldsm_x4(uint32_t& r0, uint32_t& r1, uint32_t& r2,
                                        uint32_t& r3, uint32_t addr) {
    asm volatile("ldmatrix.sync.aligned.m8n8.x4.shared.b16 {%0,%1,%2,%3}, [%4];"
                 : "=r"(r0), "=r"(r1), "=r"(r2), "=r"(r3) : "r"(addr));
}
__device__ __forceinline__ void ldsm_x2(uint32_t& r0, uint32_t& r1, uint32_t addr) {
    asm volatile("ldmatrix.sync.aligned.m8n8.x2.shared.b16 {%0,%1}, [%2];"
                 : "=r"(r0), "=r"(r1) : "r"(addr));
}
__device__ __forceinline__ void ldsm_x2t(uint32_t& r0, uint32_t& r1, uint32_t addr) {
    asm volatile("ldmatrix.sync.aligned.m8n8.x2.trans.shared.b16 {%0,%1}, [%2];"
                 : "=r"(r0), "=r"(r1) : "r"(addr));
}
__device__ __forceinline__ void mma_bf16(float* c, uint32_t a0, uint32_t a1,
                                         uint32_t a2, uint32_t a3,
                                         uint32_t b0, uint32_t b1) {
    asm volatile(
        "mma.sync.aligned.m16n8k16.row.col.f32.bf16.bf16.f32 "
        "{%0,%1,%2,%3}, {%4,%5,%6,%7}, {%8,%9}, {%0,%1,%2,%3};"
        : "+f"(c[0]), "+f"(c[1]), "+f"(c[2]), "+f"(c[3])
        : "r"(a0), "r"(a1), "r"(a2), "r"(a3), "r"(b0), "r"(b1));
}
__device__ __forceinline__ uint32_t pack_hi(float x, float y) {
    return (__float_as_uint(x) >> 16) | (__float_as_uint(y) & 0xFFFF0000u);
}
__device__ __forceinline__ uint32_t pack_lo(float x, float y) {
    float xh = __uint_as_float(__float_as_uint(x) & 0xFFFF0000u);
    float yh = __uint_as_float(__float_as_uint(y) & 0xFFFF0000u);
    __nv_bfloat162 t = __floats2bfloat162_rn(x - xh, y - yh);
    return *reinterpret_cast<uint32_t*>(&t);
}
__device__ __forceinline__ void cp16(uint32_t dst, const void* src) {
    asm volatile("cp.async.cg.shared.global [%0], [%1], 16;" :: "r"(dst), "l"(src));
}
__device__ __forceinline__ void cp_commit() {
    asm volatile("cp.async.commit_group;" ::: "memory");
}
__device__ __forceinline__ void cp_wait1() {
    asm volatile("cp.async.wait_group 1;" ::: "memory");
}
__device__ __forceinline__ void cp_wait0() {
    asm volatile("cp.async.wait_group 0;" ::: "memory");
}

/* ================= LayerNorm -> bf16 hi/lo planes ================= */
__global__ __launch_bounds__(256) void ln_kernel(const float* __restrict__ x,
                                                 const float* __restrict__ gamma,
                                                 const float* __restrict__ beta) {
    int row = blockIdx.x;
    int col = threadIdx.x * 4;
    const float* xr = x + (size_t)row * D_MODEL;

    float4 v = *(const float4*)(xr + col);
    float s = v.x + v.y + v.z + v.w;
    float ss = v.x * v.x + v.y * v.y + v.z * v.z + v.w * v.w;

    __shared__ float rs[8], rss[8];
#pragma unroll
    for (int o = 16; o > 0; o >>= 1) {
        s  += __shfl_xor_sync(0xffffffffu, s, o);
        ss += __shfl_xor_sync(0xffffffffu, ss, o);
    }
    if ((threadIdx.x & 31) == 0) { rs[threadIdx.x >> 5] = s; rss[threadIdx.x >> 5] = ss; }
    __syncthreads();
    if (threadIdx.x < 32) {
        s  = (threadIdx.x < 8) ? rs[threadIdx.x]  : 0.f;
        ss = (threadIdx.x < 8) ? rss[threadIdx.x] : 0.f;
#pragma unroll
        for (int o = 4; o > 0; o >>= 1) {
            s  += __shfl_xor_sync(0xffffffffu, s, o);
            ss += __shfl_xor_sync(0xffffffffu, ss, o);
        }
        if (threadIdx.x == 0) { rs[0] = s; rss[0] = ss; }
    }
    __syncthreads();
    float mean = rs[0] * (1.f / D_MODEL);
    float var  = rss[0] * (1.f / D_MODEL) - mean * mean;
    float rstd = rsqrtf(var + 1e-5f);

    float4 g = *(const float4*)(gamma + col);
    float4 be = *(const float4*)(beta + col);
    float4 o;
    o.x = (v.x - mean) * rstd * g.x + be.x;
    o.y = (v.y - mean) * rstd * g.y + be.y;
    o.z = (v.z - mean) * rstd * g.z + be.z;
    o.w = (v.w - mean) * rstd * g.w + be.w;

    size_t off = (size_t)row * D_MODEL + col;
    *(uint32_t*)&g_xn_hi[off]     = pack_hi(o.x, o.y);
    *(uint32_t*)&g_xn_hi[off + 2] = pack_hi(o.z, o.w);
    *(uint32_t*)&g_xn_lo[off]     = pack_lo(o.x, o.y);
    *(uint32_t*)&g_xn_lo[off + 2] = pack_lo(o.z, o.w);
}

/* ================= W -> bf16 hi/lo (one-shot) ================= */
__global__ __launch_bounds__(256) void wconv_kernel(const float* __restrict__ w) {
    size_t i = ((size_t)blockIdx.x * 256 + threadIdx.x) * 4;
    float4 v = *(const float4*)(w + i);
    *(uint32_t*)&g_w_hi[i]     = pack_hi(v.x, v.y);
    *(uint32_t*)&g_w_hi[i + 2] = pack_hi(v.z, v.w);
    *(uint32_t*)&g_w_lo[i]     = pack_lo(v.x, v.y);
    *(uint32_t*)&g_w_lo[i + 2] = pack_lo(v.z, v.w);
}

/* ========== QKV GEMM: bf16 planes, cp.async double buffer ==========
   CTA 128x128, BK=64, 8 warps (2x4), warp tile 64x32. */
#define GP 72
#define G_PLANE (128 * GP)                 /* ushorts per plane */
#define G_BUF (4 * G_PLANE)                /* Ah Al Bh Bl */
#define GEMM_SMEM (2 * G_BUF * (int)sizeof(unsigned short))  /* 147456 */

__global__ __launch_bounds__(256) void qkv_gemm(const float* __restrict__ bias) {
    extern __shared__ unsigned short smem[];
    int tid = threadIdx.x;
    int lane = tid & 31, wrp = tid >> 5;
    int wm = (wrp >> 2) * 64, wn = (wrp & 3) * 32;
    int t4 = lane >> 2, qp = lane & 3;
    int l16 = lane & 15;

    int m0 = blockIdx.y * 128;
    int n0 = blockIdx.x * 128;

    float acc[4][4][4];
#pragma unroll
    for (int i = 0; i < 4; i++)
#pragma unroll
        for (int j = 0; j < 4; j++)
#pragma unroll
            for (int c = 0; c < 4; c++) acc[i][j][c] = 0.f;

    auto load_tile = [&](int it, int buf) {
        int k0 = it * 64;
        unsigned short* Ah = smem + buf * G_BUF;
        unsigned short* Al = Ah + G_PLANE;
        unsigned short* Bh = Al + G_PLANE;
        unsigned short* Bl = Bh + G_PLANE;
#pragma unroll
        for (int i = 0; i < 4; i++) {
            int chunk = tid + i * 256;        /* 0..1023 */
            int row = chunk >> 3, seg = chunk & 7;
            size_t asrc = (size_t)(m0 + row) * D_MODEL + k0 + seg * 8;
            size_t bsrc = (size_t)(n0 + row) * D_MODEL + k0 + seg * 8;
            uint32_t d = row * GP + seg * 8;
            cp16(smem_u32(&Ah[d]), &g_xn_hi[asrc]);
            cp16(smem_u32(&Al[d]), &g_xn_lo[asrc]);
            cp16(smem_u32(&Bh[d]), &g_w_hi[bsrc]);
            cp16(smem_u32(&Bl[d]), &g_w_lo[bsrc]);
        }
    };

    load_tile(0, 0);
    cp_commit();

    for (int it = 0; it < D_MODEL / 64; it++) {
        if (it + 1 < D_MODEL / 64) { load_tile(it + 1, (it + 1) & 1); cp_commit(); cp_wait1(); }
        else cp_wait0();
        __syncthreads();

        unsigned short* Ah = smem + (it & 1) * G_BUF;
        unsigned short* Al = Ah + G_PLANE;
        unsigned short* Bh = Al + G_PLANE;
        unsigned short* Bl = Bh + G_PLANE;
#pragma unroll
        for (int ks = 0; ks < 4; ks++) {
            uint32_t ah[4][4], al[4][4];
            int acol = ks * 16 + (lane >> 4) * 8;
#pragma unroll
            for (int mt = 0; mt < 4; mt++) {
                int arow = wm + mt * 16 + l16;
                ldsm_x4(ah[mt][0], ah[mt][1], ah[mt][2], ah[mt][3],
                        smem_u32(&Ah[arow * GP + acol]));
                ldsm_x4(al[mt][0], al[mt][1], al[mt][2], al[mt][3],
                        smem_u32(&Al[arow * GP + acol]));
            }
#pragma unroll
            for (int nt = 0; nt < 4; nt++) {
                int brow = wn + nt * 8 + (l16 & 7);
                int bcol = ks * 16 + (l16 >> 3) * 8;
                uint32_t bh0, bh1, bl0, bl1;
                ldsm_x2(bh0, bh1, smem_u32(&Bh[brow * GP + bcol]));
                ldsm_x2(bl0, bl1, smem_u32(&Bl[brow * GP + bcol]));
#pragma unroll
                for (int mt = 0; mt < 4; mt++) {
                    mma_bf16(acc[mt][nt], ah[mt][0], ah[mt][1], ah[mt][2], ah[mt][3], bh0, bh1);
                    mma_bf16(acc[mt][nt], ah[mt][0], ah[mt][1], ah[mt][2], ah[mt][3], bl0, bl1);
                    mma_bf16(acc[mt][nt], al[mt][0], al[mt][1], al[mt][2], al[mt][3], bh0, bh1);
                }
            }
        }
        __syncthreads();
    }

    /* epilogue: bias, (Q scale), split to bf16 hi/lo planes */
#pragma unroll
    for (int mt = 0; mt < 4; mt++) {
        int mbase = m0 + wm + mt * 16 + t4;
#pragma unroll
        for (int nt = 0; nt < 4; nt++) {
            int n = n0 + wn + nt * 8 + qp * 2;
            int t = n >> 10;
            int hd = n & 1023;
            int h = hd >> 6, d = hd & 63;
            unsigned short *dh, *dl;
            float sc = 1.f;
            if (t == 0) { dh = g_qh; dl = g_ql; sc = 0.125f; }
            else if (t == 1) { dh = g_kh; dl = g_kl; }
            else { dh = g_vh; dl = g_vl; }
            float bv0 = bias[n], bv1 = bias[n + 1];
#pragma unroll
            for (int rr = 0; rr < 2; rr++) {
                int m = mbase + rr * 8;
                int bb = m >> 11, l = m & 2047;
                float c0 = (acc[mt][nt][2 * rr]     + bv0) * sc;
                float c1 = (acc[mt][nt][2 * rr + 1] + bv1) * sc;
                size_t off = ((((size_t)bb * NHEAD + h) * SEQ) + l) * HEAD_DIM + d;
                *(uint32_t*)&dh[off] = pack_hi(c0, c1);
                *(uint32_t*)&dl[off] = pack_lo(c0, c1);
            }
        }
    }
}

/* ========== Flash attention: bf16 planes, cp.async double-buffered KV ========== */
#define AQ 128
#define AP 72
#define A_QPLANE (AQ * AP)                 /* 9216 ushorts */
#define A_KVPLANE (64 * AP)                /* 4608 ushorts */
#define A_KVBUF (4 * A_KVPLANE)            /* Kh Kl Vh Vl */
#define ATTN_SMEM ((2 * A_QPLANE + 2 * A_KVBUF) * (int)sizeof(unsigned short)) /* 110592 */

__global__ __launch_bounds__(256) void attn_kernel(float* __restrict__ out) {
    extern __shared__ unsigned short smem[];
    unsigned short* Qh = smem;
    unsigned short* Ql = Qh + A_QPLANE;
    unsigned short* KV = Ql + A_QPLANE;

    int bh = blockIdx.y;
    int b = bh / NHEAD, h = bh % NHEAD;
    int q0 = blockIdx.x * AQ;
    size_t bhoff = (size_t)bh * SEQ * HEAD_DIM;

    int tid = threadIdx.x;
    int lane = tid & 31, wrp = tid >> 5;
    int t4 = lane >> 2, qp = lane & 3;
    int l16 = lane & 15;

    auto load_kv = [&](int kt, int buf) {
        int k0 = kt * 64;
        unsigned short* Kh = KV + buf * A_KVBUF;
        unsigned short* Kl = Kh + A_KVPLANE;
        unsigned short* Vh = Kl + A_KVPLANE;
        unsigned short* Vl = Vh + A_KVPLANE;
#pragma unroll
        for (int i = 0; i < 2; i++) {
            int chunk = tid + i * 256;        /* 0..511 */
            int row = chunk >> 3, seg = chunk & 7;
            size_t src = bhoff + (size_t)(k0 + row) * HEAD_DIM + seg * 8;
            uint32_t d = row * AP + seg * 8;
            cp16(smem_u32(&Kh[d]), &g_kh[src]);
            cp16(smem_u32(&Kl[d]), &g_kl[src]);
            cp16(smem_u32(&Vh[d]), &g_vh[src]);
            cp16(smem_u32(&Vl[d]), &g_vl[src]);
        }
    };

    /* Q planes + first KV tile in group 0 */
#pragma unroll
    for (int i = 0; i < 4; i++) {
        int chunk = tid + i * 256;            /* 0..1023 */
        int row = chunk >> 3, seg = chunk & 7;
        size_t src = bhoff + (size_t)(q0 + row) * HEAD_DIM + seg * 8;
        uint32_t d = row * AP + seg * 8;
        cp16(smem_u32(&Qh[d]), &g_qh[src]);
        cp16(smem_u32(&Ql[d]), &g_ql[src]);
    }
    load_kv(0, 0);
    cp_commit();

    float m_i[2] = {-1e30f, -1e30f};
    float l_i[2] = {0.f, 0.f};
    float O[8][4];
#pragma unroll
    for (int i = 0; i < 8; i++)
#pragma unroll
        for (int c = 0; c < 4; c++) O[i][c] = 0.f;

    for (int kt = 0; kt < SEQ / 64; kt++) {
        if (kt + 1 < SEQ / 64) { load_kv(kt + 1, (kt + 1) & 1); cp_commit(); cp_wait1(); }
        else cp_wait0();
        __syncthreads();

        unsigned short* Kh = KV + (kt & 1) * A_KVBUF;
        unsigned short* Kl = Kh + A_KVPLANE;
        unsigned short* Vh = Kl + A_KVPLANE;
        unsigned short* Vl = Vh + A_KVPLANE;

        float S[8][4];
#pragma unroll
        for (int i = 0; i < 8; i++)
#pragma unroll
            for (int c = 0; c < 4; c++) S[i][c] = 0.f;

#pragma unroll
        for (int ks = 0; ks < 4; ks++) {
            int arow = wrp * 16 + l16;
            int acol = ks * 16 + (lane >> 4) * 8;
            uint32_t qh0, qh1, qh2, qh3, ql0, ql1, ql2, ql3;
            ldsm_x4(qh0, qh1, qh2, qh3, smem_u32(&Qh[arow * AP + acol]));
            ldsm_x4(ql0, ql1, ql2, ql3, smem_u32(&Ql[arow * AP + acol]));
#pragma unroll
            for (int nt = 0; nt < 8; nt++) {
                int brow = nt * 8 + (l16 & 7);
                int bcol = ks * 16 + (l16 >> 3) * 8;
                uint32_t kh0, kh1, kl0, kl1;
                ldsm_x2(kh0, kh1, smem_u32(&Kh[brow * AP + bcol]));
                ldsm_x2(kl0, kl1, smem_u32(&Kl[brow * AP + bcol]));
                mma_bf16(S[nt], qh0, qh1, qh2, qh3, kh0, kh1);
                mma_bf16(S[nt], qh0, qh1, qh2, qh3, kl0, kl1);
                mma_bf16(S[nt], ql0, ql1, ql2, ql3, kh0, kh1);
            }
        }

        float mx0 = S[0][0], mx1 = S[0][2];
#pragma unroll
        for (int nt = 0; nt < 8; nt++) {
            mx0 = fmaxf(mx0, fmaxf(S[nt][0], S[nt][1]));
            mx1 = fmaxf(mx1, fmaxf(S[nt][2], S[nt][3]));
        }
#pragma unroll
        for (int o = 1; o <= 2; o <<= 1) {
            mx0 = fmaxf(mx0, __shfl_xor_sync(0xffffffffu, mx0, o));
            mx1 = fmaxf(mx1, __shfl_xor_sync(0xffffffffu, mx1, o));
        }
        float mn0 = fmaxf(m_i[0], mx0), mn1 = fmaxf(m_i[1], mx1);
        float al0 = __expf(m_i[0] - mn0), al1 = __expf(m_i[1] - mn1);
        float sum0 = 0.f, sum1 = 0.f;
#pragma unroll
        for (int nt = 0; nt < 8; nt++) {
            S[nt][0] = __expf(S[nt][0] - mn0);
            S[nt][1] = __expf(S[nt][1] - mn0);
            S[nt][2] = __expf(S[nt][2] - mn1);
            S[nt][3] = __expf(S[nt][3] - mn1);
            sum0 += S[nt][0] + S[nt][1];
            sum1 += S[nt][2] + S[nt][3];
        }
#pragma unroll
        for (int o = 1; o <= 2; o <<= 1) {
            sum0 += __shfl_xor_sync(0xffffffffu, sum0, o);
            sum1 += __shfl_xor_sync(0xffffffffu, sum1, o);
        }
        l_i[0] = l_i[0] * al0 + sum0;
        l_i[1] = l_i[1] * al1 + sum1;
        m_i[0] = mn0; m_i[1] = mn1;
#pragma unroll
        for (int dn = 0; dn < 8; dn++) {
            O[dn][0] *= al0; O[dn][1] *= al0;
            O[dn][2] *= al1; O[dn][3] *= al1;
        }

#pragma unroll
        for (int ks2 = 0; ks2 < 4; ks2++) {
            uint32_t ph0 = pack_hi(S[2 * ks2][0],     S[2 * ks2][1]);
            uint32_t ph1 = pack_hi(S[2 * ks2][2],     S[2 * ks2][3]);
            uint32_t ph2 = pack_hi(S[2 * ks2 + 1][0], S[2 * ks2 + 1][1]);
            uint32_t ph3 = pack_hi(S[2 * ks2 + 1][2], S[2 * ks2 + 1][3]);
            uint32_t pl0 = pack_lo(S[2 * ks2][0],     S[2 * ks2][1]);
            uint32_t pl1 = pack_lo(S[2 * ks2][2],     S[2 * ks2][3]);
            uint32_t pl2 = pack_lo(S[2 * ks2 + 1][0], S[2 * ks2 + 1][1]);
            uint32_t pl3 = pack_lo(S[2 * ks2 + 1][2], S[2 * ks2 + 1][3]);
            int vrow = ks2 * 16 + (l16 & 7) + (l16 >> 3) * 8;
#pragma unroll
            for (int dn = 0; dn < 8; dn++) {
                uint32_t vh0, vh1, vl0, vl1;
                ldsm_x2t(vh0, vh1, smem_u32(&Vh[vrow * AP + dn * 8]));
                ldsm_x2t(vl0, vl1, smem_u32(&Vl[vrow * AP + dn * 8]));
                mma_bf16(O[dn], ph0, ph1, ph2, ph3, vh0, vh1);
                mma_bf16(O[dn], ph0, ph1, ph2, ph3, vl0, vl1);
                mma_bf16(O[dn], pl0, pl1, pl2, pl3, vh0, vh1);
            }
        }
        __syncthreads();
    }

    float inv0 = 1.f / l_i[0], inv1 = 1.f / l_i[1];
    int r0 = q0 + wrp * 16 + t4, r1 = r0 + 8;
#pragma unroll
    for (int dn = 0; dn < 8; dn++) {
        int d = h * 64 + dn * 8 + qp * 2;
        float2 v0 = make_float2(O[dn][0] * inv0, O[dn][1] * inv0);
        float2 v1 = make_float2(O[dn][2] * inv1, O[dn][3] * inv1);
        *(float2*)&out[((size_t)b * SEQ + r0) * D_MODEL + d] = v0;
        *(float2*)&out[((size_t)b * SEQ + r1) * D_MODEL + d] = v1;
    }
}

/* ======================= launch ======================= */
extern "C" void kernel_launch(void* const* d_in, const int* in_sizes, int n_in,
                              void* d_out, int out_size) {
    const float* x     = (const float*)d_in[0];
    const float* w_qkv = (const float*)d_in[1];
    const float* b_qkv = (const float*)d_in[2];
    const float* gamma = (const float*)d_in[3];
    const float* beta  = (const float*)d_in[4];
    float* out = (float*)d_out;

    (void)in_sizes; (void)n_in; (void)out_size;

    cudaFuncSetAttribute(qkv_gemm, cudaFuncAttributeMaxDynamicSharedMemorySize,
                         GEMM_SMEM);
    cudaFuncSetAttribute(attn_kernel, cudaFuncAttributeMaxDynamicSharedMemorySize,
                         ATTN_SMEM);

    ln_kernel<<<M_TOTAL, 256>>>(x, gamma, beta);
    wconv_kernel<<<(N_QKV * D_MODEL) / 1024, 256>>>(w_qkv);

    dim3 ggrid(N_QKV / 128, M_TOTAL / 128);   /* 24 x 32 */
    qkv_gemm<<<ggrid, 256, GEMM_SMEM>>>(b_qkv);

    dim3 agrid(SEQ / AQ, BATCH * NHEAD);      /* 16 x 32 */
    attn_kernel<<<agrid, 256, ATTN_SMEM>>>(out);
}